// round 8
// baseline (speedup 1.0000x reference)
#include <cuda_runtime.h>
#include <cuda_fp16.h>
#include <math.h>
#include <stdint.h>

#define T_DIM 4096
#define H_DIM 1024
#define E_DIM 8
#define I_DIM 2048
#define STAGES 3

// ---------------- scratch (static device globals) ----------------
__device__ __half g_normed_h[(size_t)T_DIM * H_DIM];          // 8 MB
__device__ __half g_act_h[(size_t)E_DIM * T_DIM * I_DIM];     // 134 MB
__device__ float  g_out2[(size_t)E_DIM * T_DIM * H_DIM];      // 134 MB
__device__ int    g_cnt[E_DIM];
__device__ int    g_tok[E_DIM * T_DIM];
__device__ int    g_slot[T_DIM * 2];
__device__ float  g_wgt[T_DIM * 2];

// ---------------- PTX helpers ----------------
__device__ __forceinline__ uint32_t smem_u32(const void* p) {
    uint32_t a;
    asm("{ .reg .u64 t; cvta.to.shared.u64 t, %1; cvt.u32.u64 %0, t; }" : "=r"(a) : "l"(p));
    return a;
}
__device__ __forceinline__ void cp16(uint32_t dst, const void* src) {
    asm volatile("cp.async.cg.shared.global [%0], [%1], 16;" :: "r"(dst), "l"(src));
}
#define CP_COMMIT() asm volatile("cp.async.commit_group;" ::: "memory")
#define CP_WAIT1()  asm volatile("cp.async.wait_group 1;" ::: "memory")
__device__ __forceinline__ void ldsm4(uint32_t* r, uint32_t addr) {
    asm volatile("ldmatrix.sync.aligned.m8n8.x4.shared.b16 {%0,%1,%2,%3}, [%4];"
        : "=r"(r[0]), "=r"(r[1]), "=r"(r[2]), "=r"(r[3]) : "r"(addr));
}
__device__ __forceinline__ void mma_f16(float* c, const uint32_t* a, const uint32_t* b) {
    asm("mma.sync.aligned.m16n8k16.row.col.f32.f16.f16.f32 "
        "{%0,%1,%2,%3},{%4,%5,%6,%7},{%8,%9},{%0,%1,%2,%3};"
        : "+f"(c[0]), "+f"(c[1]), "+f"(c[2]), "+f"(c[3])
        : "r"(a[0]), "r"(a[1]), "r"(a[2]), "r"(a[3]), "r"(b[0]), "r"(b[1]));
}
__device__ __forceinline__ uint32_t f2h2(float a, float b) {
    __half2 h = __floats2half2_rn(a, b);
    return *(uint32_t*)&h;
}
__device__ __forceinline__ float swiglu(float gv, float lv) {
    gv = fminf(gv, 7.f);
    lv = fminf(fmaxf(lv, -7.f), 7.f);
    const float sw = gv / (1.f + expf(-1.702f * gv));
    return sw * (lv + 1.f);
}

// ---------------- kernel 0: reset routing counters ----------------
__global__ void k_zero() {
    if (threadIdx.x < E_DIM) g_cnt[threadIdx.x] = 0;
}

// ---------------- kernel 1: RMSNorm + gate + top-2 + routing ----------------
// 32 tokens per block (128 blocks); warp w handles tokens base + 4w .. +3.
// gk staged once per block in SMEM with 16B-chunk swizzle (4-phase optimal reads).
// Routing atomics aggregated: 8 atomicAdds per block.
__global__ __launch_bounds__(256) void k_rms_gate(
    const float* __restrict__ x, const float* __restrict__ scale,
    const float* __restrict__ gk, const float* __restrict__ gb)
{
    __shared__ float4 sgk4[2048];   // 32 KB swizzled gk
    __shared__ int    sti[64];
    __shared__ float  stw[64];

    const int tid = threadIdx.x, lane = tid & 31, wid = tid >> 5;

    const float4* gk4 = (const float4*)gk;
#pragma unroll
    for (int q = tid; q < 2048; q += 256)
        sgk4[q ^ ((q >> 3) & 1)] = gk4[q];
    __syncthreads();

#pragma unroll
    for (int it = 0; it < 4; it++) {
        const int t = blockIdx.x * 32 + wid * 4 + it;
        const float* xrow = x + (size_t)t * H_DIM;

        float xr[32];
        float ss = 0.f;
#pragma unroll
        for (int j = 0; j < 32; j++) {
            xr[j] = xrow[j * 32 + lane];
            ss += xr[j] * xr[j];
        }
#pragma unroll
        for (int o = 16; o > 0; o >>= 1) ss += __shfl_xor_sync(0xffffffffu, ss, o);
        const float rinv = rsqrtf(ss * (1.0f / H_DIM) + 1e-5f);

        __half* nrow = g_normed_h + (size_t)t * H_DIM;
#pragma unroll
        for (int j = 0; j < 32; j++) {
            const int h = j * 32 + lane;
            xr[j] = xr[j] * rinv * __ldg(scale + h);
            nrow[h] = __float2half_rn(xr[j]);
        }

        float acc[8];
#pragma unroll
        for (int e2 = 0; e2 < 8; e2++) acc[e2] = 0.f;
#pragma unroll
        for (int j = 0; j < 32; j++) {
            const int h = j * 32 + lane;
            const int b = (h >> 2) & 1;
            const float4 g0 = sgk4[(2 * h) ^ b];
            const float4 g1 = sgk4[(2 * h + 1) ^ b];
            const float nv = xr[j];
            acc[0] += nv * g0.x; acc[1] += nv * g0.y;
            acc[2] += nv * g0.z; acc[3] += nv * g0.w;
            acc[4] += nv * g1.x; acc[5] += nv * g1.y;
            acc[6] += nv * g1.z; acc[7] += nv * g1.w;
        }
#pragma unroll
        for (int e2 = 0; e2 < 8; e2++) {
#pragma unroll
            for (int o = 16; o > 0; o >>= 1)
                acc[e2] += __shfl_xor_sync(0xffffffffu, acc[e2], o);
        }

        if (lane == 0) {
            float lg[8];
#pragma unroll
            for (int e2 = 0; e2 < 8; e2++) lg[e2] = acc[e2] + __ldg(gb + e2);
            int i0 = 0; float l0 = lg[0];
#pragma unroll
            for (int e2 = 1; e2 < 8; e2++) { if (lg[e2] > l0) { l0 = lg[e2]; i0 = e2; } }
            int i1 = -1; float l1 = -3.4e38f;
#pragma unroll
            for (int e2 = 0; e2 < 8; e2++) {
                if (e2 != i0 && lg[e2] > l1) { l1 = lg[e2]; i1 = e2; }
            }
            const float m  = fmaxf(l0, l1);
            const float e0 = expf(l0 - m), e1f = expf(l1 - m);
            const float inv = 1.0f / (e0 + e1f);
            const int bt = wid * 4 + it;
            sti[2 * bt + 0] = i0; stw[2 * bt + 0] = e0 * inv;
            sti[2 * bt + 1] = i1; stw[2 * bt + 1] = e1f * inv;
        }
    }
    __syncthreads();

    if (tid < 8) {
        const int e = tid;
        int cnt = 0;
#pragma unroll
        for (int k = 0; k < 64; k++) cnt += (sti[k] == e) ? 1 : 0;
        int base = atomicAdd(&g_cnt[e], cnt);
        for (int k = 0; k < 64; k++) {
            if (sti[k] == e) {
                const int bt = k >> 1, ch = k & 1;
                const int t = blockIdx.x * 32 + bt;
                const int slot = e * T_DIM + base;
                g_tok[slot] = t;
                g_slot[2 * t + ch] = slot;
                g_wgt[2 * t + ch] = stw[k];
                base++;
            }
        }
    }
}

// ======================= GEMM kernels =======================
// A: fp16 via cp.async (3-stage). B: fp32 weights, reg-prefetched one K-tile
// ahead, converted to fp16 at STS time. Stage = A 16KB + B 16KB = 32KB.
#define STAGE_BYTES 32768
#define G1_SMEM (1024 + STAGES * STAGE_BYTES)
#define G2_SMEM (1024 + STAGES * STAGE_BYTES)

// ---------------- kernel 2: grouped GEMM1 + SwiGLU -> g_act_h ----------------
__global__ __launch_bounds__(256) void k_gemm1(const float* __restrict__ w1,
                                               const float* __restrict__ b1)
{
    extern __shared__ char smem[];
    const int e  = blockIdx.z;
    const int ne = g_cnt[e];
    const int m0 = blockIdx.y * 128;
    if (m0 >= ne) return;
    const int n0 = blockIdx.x * 64;
    const int tid = threadIdx.x, lane = tid & 31, wid = tid >> 5;
    const int wm = wid >> 2, wn = wid & 3;
    const uint32_t sb = smem_u32(smem);

    int* stok = (int*)smem;
    if (tid < 128) {
        const int m = m0 + tid;
        stok[tid] = g_tok[e * T_DIM + (m < ne ? m : ne - 1)];
    }
    __syncthreads();

    const int c8  = tid & 7;
    const int r32 = tid >> 3;
    const uint32_t swz = (uint32_t)((c8 ^ (r32 & 7)) << 4);
    const __half* asrc[4];
    uint32_t adst[4];
    const float* bsrcf[4];
    uint32_t boff[4];
#pragma unroll
    for (int i = 0; i < 4; i++) {
        const int row = r32 + i * 32;
        asrc[i] = g_normed_h + (size_t)stok[row] * H_DIM + c8 * 8;
        adst[i] = sb + 1024u + (uint32_t)row * 128u + swz;
        const int grow = (row < 64) ? (n0 + row) : (I_DIM + n0 + row - 64);
        bsrcf[i] = w1 + ((size_t)e * 2 * I_DIM + grow) * H_DIM + c8 * 8;
        boff[i] = 1024u + (uint32_t)row * 128u + swz + 16384u;
    }

#define G1_ISSA(kt, s) do { \
    const uint32_t so = (uint32_t)(s) * STAGE_BYTES; \
    const int ko = (kt) * 64; \
    _Pragma("unroll") \
    for (int i = 0; i < 4; i++) cp16(adst[i] + so, asrc[i] + ko); \
    } while (0)
#define G1_LDGB(kt) do { \
    const int ko = (kt) * 64; \
    _Pragma("unroll") \
    for (int i = 0; i < 4; i++) { \
        braw[2*i]   = *(const float4*)(bsrcf[i] + ko); \
        braw[2*i+1] = *(const float4*)(bsrcf[i] + ko + 4); \
    } } while (0)
#define G1_STSB(s) do { \
    _Pragma("unroll") \
    for (int i = 0; i < 4; i++) { \
        uint4 u; \
        u.x = f2h2(braw[2*i].x,   braw[2*i].y); \
        u.y = f2h2(braw[2*i].z,   braw[2*i].w); \
        u.z = f2h2(braw[2*i+1].x, braw[2*i+1].y); \
        u.w = f2h2(braw[2*i+1].z, braw[2*i+1].w); \
        *(uint4*)(smem + boff[i] + (uint32_t)(s) * STAGE_BYTES) = u; \
    } } while (0)

    const int NK = H_DIM / 64;   // 16
    G1_ISSA(0, 0); CP_COMMIT();
    G1_ISSA(1, 1); CP_COMMIT();
    float4 braw[8];
    G1_LDGB(0);

    float accg[4][2][4] = {}, accl[4][2][4] = {};

    const int lr  = lane & 7;
    const int rA  = ((lane >> 3) & 1) * 8 + lr;
    const int cA  = (lane >> 4);
    const int rB  = ((lane >> 4) & 1) * 8 + lr;
    const int cB  = ((lane >> 3) & 1);

    for (int c = 0; c < NK; c++) {
        G1_STSB(c % 3);
        CP_WAIT1();
        __syncthreads();
        if (c + 1 < NK) G1_LDGB(c + 1);
        if (c + 2 < NK) G1_ISSA(c + 2, (c + 2) % 3);
        CP_COMMIT();

        const uint32_t Asm = sb + 1024u + (uint32_t)(c % 3) * STAGE_BYTES;
        const uint32_t Bsm = Asm + 16384u;
#pragma unroll
        for (int ks = 0; ks < 4; ks++) {
            uint32_t a[4][4];
            const uint32_t chA = (uint32_t)(((2 * ks + cA) ^ lr) << 4);
#pragma unroll
            for (int mf = 0; mf < 4; mf++) {
                const int row = wm * 64 + mf * 16 + rA;
                ldsm4(a[mf], Asm + (uint32_t)row * 128u + chA);
            }
            uint32_t bg[4], bl[4];
            const uint32_t chB = (uint32_t)(((2 * ks + cB) ^ lr) << 4);
            ldsm4(bg, Bsm + (uint32_t)(wn * 16 + rB) * 128u + chB);
            ldsm4(bl, Bsm + (uint32_t)(64 + wn * 16 + rB) * 128u + chB);
#pragma unroll
            for (int mf = 0; mf < 4; mf++) {
#pragma unroll
                for (int nf = 0; nf < 2; nf++) {
                    mma_f16(accg[mf][nf], a[mf], bg + 2 * nf);
                    mma_f16(accl[mf][nf], a[mf], bl + 2 * nf);
                }
            }
        }
    }

    const float* bgb = b1 + (size_t)e * 2 * I_DIM + n0;
    const float* blb = bgb + I_DIM;
#pragma unroll
    for (int mf = 0; mf < 4; mf++) {
        const int mb = m0 + wm * 64 + mf * 16 + (lane >> 2);
#pragma unroll
        for (int h = 0; h < 2; h++) {
            const int m = mb + h * 8;
            if (m < ne) {
                __half* orow = g_act_h + ((size_t)e * T_DIM + m) * I_DIM + n0;
#pragma unroll
                for (int nf = 0; nf < 2; nf++) {
                    const int nloc = wn * 16 + nf * 8 + 2 * (lane & 3);
                    const float g0 = accg[mf][nf][2 * h + 0] + bgb[nloc];
                    const float g1 = accg[mf][nf][2 * h + 1] + bgb[nloc + 1];
                    const float l0 = accl[mf][nf][2 * h + 0] + blb[nloc];
                    const float l1 = accl[mf][nf][2 * h + 1] + blb[nloc + 1];
                    __half2 o = __floats2half2_rn(swiglu(g0, l0), swiglu(g1, l1));
                    *(__half2*)(orow + nloc) = o;
                }
            }
        }
    }
#undef G1_ISSA
#undef G1_LDGB
#undef G1_STSB
}

// ---------------- kernel 3: grouped GEMM2 + bias -> g_out2 (fp32) ----------------
__global__ __launch_bounds__(256) void k_gemm2(const float* __restrict__ w2,
                                               const float* __restrict__ b2)
{
    extern __shared__ char smem[];
    const int e  = blockIdx.z;
    const int ne = g_cnt[e];
    const int m0 = blockIdx.y * 128;
    if (m0 >= ne) return;
    const int n0 = blockIdx.x * 128;
    const int tid = threadIdx.x, lane = tid & 31, wid = tid >> 5;
    const int wm = wid >> 2, wn = wid & 3;
    const uint32_t sb = smem_u32(smem);

    const __half* a_base = g_act_h + ((size_t)e * T_DIM + m0) * I_DIM;
    const float*  b_basef = w2 + ((size_t)e * H_DIM + n0) * I_DIM;

    const int c8  = tid & 7;
    const int r32 = tid >> 3;
    const uint32_t swz = (uint32_t)((c8 ^ (r32 & 7)) << 4);
    const __half* asrc[4];
    uint32_t adst[4];
    const float* bsrcf[4];
    uint32_t boff[4];
#pragma unroll
    for (int i = 0; i < 4; i++) {
        const int row = r32 + i * 32;
        asrc[i] = a_base + (size_t)row * I_DIM + c8 * 8;
        adst[i] = sb + 1024u + (uint32_t)row * 128u + swz;
        bsrcf[i] = b_basef + (size_t)row * I_DIM + c8 * 8;
        boff[i] = 1024u + (uint32_t)row * 128u + swz + 16384u;
    }

#define G2_ISSA(kt, s) do { \
    const uint32_t so = (uint32_t)(s) * STAGE_BYTES; \
    const int ko = (kt) * 64; \
    _Pragma("unroll") \
    for (int i = 0; i < 4; i++) cp16(adst[i] + so, asrc[i] + ko); \
    } while (0)
#define G2_LDGB(kt) do { \
    const int ko = (kt) * 64; \
    _Pragma("unroll") \
    for (int i = 0; i < 4; i++) { \
        braw[2*i]   = *(const float4*)(bsrcf[i] + ko); \
        braw[2*i+1] = *(const float4*)(bsrcf[i] + ko + 4); \
    } } while (0)
#define G2_STSB(s) do { \
    _Pragma("unroll") \
    for (int i = 0; i < 4; i++) { \
        uint4 u; \
        u.x = f2h2(braw[2*i].x,   braw[2*i].y); \
        u.y = f2h2(braw[2*i].z,   braw[2*i].w); \
        u.z = f2h2(braw[2*i+1].x, braw[2*i+1].y); \
        u.w = f2h2(braw[2*i+1].z, braw[2*i+1].w); \
        *(uint4*)(smem + boff[i] + (uint32_t)(s) * STAGE_BYTES) = u; \
    } } while (0)

    const int NK = I_DIM / 64;   // 32
    G2_ISSA(0, 0); CP_COMMIT();
    G2_ISSA(1, 1); CP_COMMIT();
    float4 braw[8];
    G2_LDGB(0);

    float acc[4][4][4] = {};

    const int lr  = lane & 7;
    const int rA  = ((lane >> 3) & 1) * 8 + lr;
    const int cA  = (lane >> 4);
    const int rB  = ((lane >> 4) & 1) * 8 + lr;
    const int cB  = ((lane >> 3) & 1);

    for (int c = 0; c < NK; c++) {
        G2_STSB(c % 3);
        CP_WAIT1();
        __syncthreads();
        if (c + 1 < NK) G2_LDGB(c + 1);
        if (c + 2 < NK) G2_ISSA(c + 2, (c + 2) % 3);
        CP_COMMIT();

        const uint32_t Asm = sb + 1024u + (uint32_t)(c % 3) * STAGE_BYTES;
        const uint32_t Bsm = Asm + 16384u;
#pragma unroll
        for (int ks = 0; ks < 4; ks++) {
            uint32_t a[4][4];
            const uint32_t chA = (uint32_t)(((2 * ks + cA) ^ lr) << 4);
#pragma unroll
            for (int mf = 0; mf < 4; mf++) {
                const int row = wm * 64 + mf * 16 + rA;
                ldsm4(a[mf], Asm + (uint32_t)row * 128u + chA);
            }
            uint32_t b[2][4];
            const uint32_t chB = (uint32_t)(((2 * ks + cB) ^ lr) << 4);
            ldsm4(b[0], Bsm + (uint32_t)(wn * 32 + rB) * 128u + chB);
            ldsm4(b[1], Bsm + (uint32_t)(wn * 32 + 16 + rB) * 128u + chB);
#pragma unroll
            for (int mf = 0; mf < 4; mf++) {
#pragma unroll
                for (int nf = 0; nf < 4; nf++)
                    mma_f16(acc[mf][nf], a[mf], b[nf >> 1] + 2 * (nf & 1));
            }
        }
    }

    const float* bb = b2 + (size_t)e * H_DIM + n0;
#pragma unroll
    for (int mf = 0; mf < 4; mf++) {
        const int mb = m0 + wm * 64 + mf * 16 + (lane >> 2);
#pragma unroll
        for (int h = 0; h < 2; h++) {
            const int m = mb + h * 8;
            if (m < ne) {
                float* orow = g_out2 + ((size_t)e * T_DIM + m) * H_DIM + n0;
#pragma unroll
                for (int nf = 0; nf < 4; nf++) {
                    const int nloc = wn * 32 + nf * 8 + 2 * (lane & 3);
                    float2 o = { acc[mf][nf][2 * h + 0] + bb[nloc],
                                 acc[mf][nf][2 * h + 1] + bb[nloc + 1] };
                    *(float2*)(orow + nloc) = o;
                }
            }
        }
    }
#undef G2_ISSA
#undef G2_LDGB
#undef G2_STSB
}

// ---------------- kernel 4: gather-combine + residual ----------------
__global__ __launch_bounds__(256) void k_combine(
    const float* __restrict__ x, float* __restrict__ out)
{
    const size_t idx = (size_t)blockIdx.x * blockDim.x + threadIdx.x;
    if (idx >= (size_t)T_DIM * H_DIM / 4) return;
    const int t  = (int)(idx / (H_DIM / 4));
    const int hc = (int)(idx % (H_DIM / 4));

    const int   s0 = g_slot[2 * t + 0], s1 = g_slot[2 * t + 1];
    const float w0 = g_wgt[2 * t + 0],  w1 = g_wgt[2 * t + 1];

    const float4 xv = ((const float4*)x)[idx];
    const float4 o0 = *(const float4*)(g_out2 + (size_t)s0 * H_DIM + hc * 4);
    const float4 o1 = *(const float4*)(g_out2 + (size_t)s1 * H_DIM + hc * 4);
    float4 o;
    o.x = xv.x + w0 * o0.x + w1 * o1.x;
    o.y = xv.y + w0 * o0.y + w1 * o1.y;
    o.z = xv.z + w0 * o0.z + w1 * o1.z;
    o.w = xv.w + w0 * o0.w + w1 * o1.w;
    ((float4*)out)[idx] = o;
}

// ---------------- launch ----------------
extern "C" void kernel_launch(void* const* d_in, const int* in_sizes, int n_in,
                              void* d_out, int out_size)
{
    const float* x     = (const float*)d_in[0];
    const float* scale = (const float*)d_in[1];
    const float* gk    = (const float*)d_in[2];
    const float* gb    = (const float*)d_in[3];
    const float* w1    = (const float*)d_in[4];
    const float* b1    = (const float*)d_in[5];
    const float* w2    = (const float*)d_in[6];
    const float* b2    = (const float*)d_in[7];
    float* out = (float*)d_out;

    cudaFuncSetAttribute(k_gemm1, cudaFuncAttributeMaxDynamicSharedMemorySize, G1_SMEM);
    cudaFuncSetAttribute(k_gemm2, cudaFuncAttributeMaxDynamicSharedMemorySize, G2_SMEM);

    k_zero<<<1, 32>>>();
    k_rms_gate<<<T_DIM / 32, 256>>>(x, scale, gk, gb);

    dim3 g1(I_DIM / 64, T_DIM / 128, E_DIM);    // 32 x 32 x 8
    k_gemm1<<<g1, 256, G1_SMEM>>>(w1, b1);

    dim3 g2(H_DIM / 128, T_DIM / 128, E_DIM);   // 8 x 32 x 8
    k_gemm2<<<g2, 256, G2_SMEM>>>(w2, b2);

    k_combine<<<(T_DIM * H_DIM / 4 + 255) / 256, 256>>>(x, out);
}

// round 9
// speedup vs baseline: 1.3666x; 1.3666x over previous
#include <cuda_runtime.h>
#include <cuda_fp16.h>
#include <math.h>
#include <stdint.h>

#define T_DIM 4096
#define H_DIM 1024
#define E_DIM 8
#define I_DIM 2048
#define STAGES 3

// ---------------- scratch (static device globals) ----------------
__device__ __half g_w1h[(size_t)E_DIM * 2 * I_DIM * H_DIM];   // 67 MB
__device__ __half g_w2h[(size_t)E_DIM * H_DIM * I_DIM];       // 33.5 MB
__device__ __half g_normed_h[(size_t)T_DIM * H_DIM];          // 8 MB
__device__ __half g_act_h[(size_t)E_DIM * T_DIM * I_DIM];     // 134 MB
__device__ float  g_out2[(size_t)E_DIM * T_DIM * H_DIM];      // 134 MB
__device__ int    g_cnt[E_DIM];
__device__ int    g_tok[E_DIM * T_DIM];
__device__ int    g_slot[T_DIM * 2];
__device__ float  g_wgt[T_DIM * 2];

// ---------------- PTX helpers ----------------
__device__ __forceinline__ uint32_t smem_u32(const void* p) {
    uint32_t a;
    asm("{ .reg .u64 t; cvta.to.shared.u64 t, %1; cvt.u32.u64 %0, t; }" : "=r"(a) : "l"(p));
    return a;
}
__device__ __forceinline__ void cp16(uint32_t dst, const void* src) {
    asm volatile("cp.async.cg.shared.global [%0], [%1], 16;" :: "r"(dst), "l"(src));
}
#define CP_COMMIT() asm volatile("cp.async.commit_group;" ::: "memory")
#define CP_WAIT1()  asm volatile("cp.async.wait_group 1;" ::: "memory")
__device__ __forceinline__ void ldsm4(uint32_t* r, uint32_t addr) {
    asm volatile("ldmatrix.sync.aligned.m8n8.x4.shared.b16 {%0,%1,%2,%3}, [%4];"
        : "=r"(r[0]), "=r"(r[1]), "=r"(r[2]), "=r"(r[3]) : "r"(addr));
}
__device__ __forceinline__ void mma_f16(float* c, const uint32_t* a, const uint32_t* b) {
    asm("mma.sync.aligned.m16n8k16.row.col.f32.f16.f16.f32 "
        "{%0,%1,%2,%3},{%4,%5,%6,%7},{%8,%9},{%0,%1,%2,%3};"
        : "+f"(c[0]), "+f"(c[1]), "+f"(c[2]), "+f"(c[3])
        : "r"(a[0]), "r"(a[1]), "r"(a[2]), "r"(a[3]), "r"(b[0]), "r"(b[1]));
}
__device__ __forceinline__ float swiglu(float gv, float lv) {
    gv = fminf(gv, 7.f);
    lv = fminf(fmaxf(lv, -7.f), 7.f);
    const float sw = gv / (1.f + expf(-1.702f * gv));
    return sw * (lv + 1.f);
}

// ---------------- kernel: fp32 -> fp16 conversion ----------------
__global__ __launch_bounds__(256) void k_cvt(const float4* __restrict__ src,
                                             uint2* __restrict__ dst, int n4)
{
    const int i = blockIdx.x * 256 + threadIdx.x;
    if (i < n4) {
        const float4 v = src[i];
        __half2 a = __floats2half2_rn(v.x, v.y);
        __half2 b = __floats2half2_rn(v.z, v.w);
        uint2 u;
        u.x = *(const uint32_t*)&a;
        u.y = *(const uint32_t*)&b;
        dst[i] = u;
    }
}

// ---------------- kernel 0: reset routing counters ----------------
__global__ void k_zero() {
    if (threadIdx.x < E_DIM) g_cnt[threadIdx.x] = 0;
}

// ---------------- kernel 1: RMSNorm + gate + top-2 + routing ----------------
// 32 tokens per block (128 blocks); warp w handles tokens base + 4w .. +3.
// gk staged once per block in SMEM (swizzled); routing atomics aggregated: 8/block.
__global__ __launch_bounds__(256) void k_rms_gate(
    const float* __restrict__ x, const float* __restrict__ scale,
    const float* __restrict__ gk, const float* __restrict__ gb)
{
    __shared__ float4 sgk4[2048];   // 32 KB swizzled gk
    __shared__ int    sti[64];
    __shared__ float  stw[64];

    const int tid = threadIdx.x, lane = tid & 31, wid = tid >> 5;

    const float4* gk4 = (const float4*)gk;
#pragma unroll
    for (int q = tid; q < 2048; q += 256)
        sgk4[q ^ ((q >> 3) & 1)] = gk4[q];
    __syncthreads();

#pragma unroll
    for (int it = 0; it < 4; it++) {
        const int t = blockIdx.x * 32 + wid * 4 + it;
        const float* xrow = x + (size_t)t * H_DIM;

        float xr[32];
        float ss = 0.f;
#pragma unroll
        for (int j = 0; j < 32; j++) {
            xr[j] = xrow[j * 32 + lane];
            ss += xr[j] * xr[j];
        }
#pragma unroll
        for (int o = 16; o > 0; o >>= 1) ss += __shfl_xor_sync(0xffffffffu, ss, o);
        const float rinv = rsqrtf(ss * (1.0f / H_DIM) + 1e-5f);

        __half* nrow = g_normed_h + (size_t)t * H_DIM;
#pragma unroll
        for (int j = 0; j < 32; j++) {
            const int h = j * 32 + lane;
            xr[j] = xr[j] * rinv * __ldg(scale + h);
            nrow[h] = __float2half_rn(xr[j]);
        }

        float acc[8];
#pragma unroll
        for (int e2 = 0; e2 < 8; e2++) acc[e2] = 0.f;
#pragma unroll
        for (int j = 0; j < 32; j++) {
            const int h = j * 32 + lane;
            const int b = (h >> 2) & 1;
            const float4 g0 = sgk4[(2 * h) ^ b];
            const float4 g1 = sgk4[(2 * h + 1) ^ b];
            const float nv = xr[j];
            acc[0] += nv * g0.x; acc[1] += nv * g0.y;
            acc[2] += nv * g0.z; acc[3] += nv * g0.w;
            acc[4] += nv * g1.x; acc[5] += nv * g1.y;
            acc[6] += nv * g1.z; acc[7] += nv * g1.w;
        }
#pragma unroll
        for (int e2 = 0; e2 < 8; e2++) {
#pragma unroll
            for (int o = 16; o > 0; o >>= 1)
                acc[e2] += __shfl_xor_sync(0xffffffffu, acc[e2], o);
        }

        if (lane == 0) {
            float lg[8];
#pragma unroll
            for (int e2 = 0; e2 < 8; e2++) lg[e2] = acc[e2] + __ldg(gb + e2);
            int i0 = 0; float l0 = lg[0];
#pragma unroll
            for (int e2 = 1; e2 < 8; e2++) { if (lg[e2] > l0) { l0 = lg[e2]; i0 = e2; } }
            int i1 = -1; float l1 = -3.4e38f;
#pragma unroll
            for (int e2 = 0; e2 < 8; e2++) {
                if (e2 != i0 && lg[e2] > l1) { l1 = lg[e2]; i1 = e2; }
            }
            const float m  = fmaxf(l0, l1);
            const float e0 = expf(l0 - m), e1f = expf(l1 - m);
            const float inv = 1.0f / (e0 + e1f);
            const int bt = wid * 4 + it;
            sti[2 * bt + 0] = i0; stw[2 * bt + 0] = e0 * inv;
            sti[2 * bt + 1] = i1; stw[2 * bt + 1] = e1f * inv;
        }
    }
    __syncthreads();

    if (tid < 8) {
        const int e = tid;
        int cnt = 0;
#pragma unroll
        for (int k = 0; k < 64; k++) cnt += (sti[k] == e) ? 1 : 0;
        int base = atomicAdd(&g_cnt[e], cnt);
        for (int k = 0; k < 64; k++) {
            if (sti[k] == e) {
                const int bt = k >> 1, ch = k & 1;
                const int t = blockIdx.x * 32 + bt;
                const int slot = e * T_DIM + base;
                g_tok[slot] = t;
                g_slot[2 * t + ch] = slot;
                g_wgt[2 * t + ch] = stw[k];
                base++;
            }
        }
    }
}

// ======================= GEMM kernels (fp16 mma + ldmatrix + cp.async) =======================
#define STAGE_BYTES 32768
#define G1_SMEM (1024 + STAGES * STAGE_BYTES)
#define G2_SMEM (1024 + STAGES * STAGE_BYTES)

// ---------------- kernel 2: grouped GEMM1 + SwiGLU -> g_act_h ----------------
__global__ __launch_bounds__(256, 2) void k_gemm1(const float* __restrict__ b1)
{
    extern __shared__ char smem[];
    const int e  = blockIdx.z;
    const int ne = g_cnt[e];
    const int m0 = blockIdx.y * 128;
    if (m0 >= ne) return;
    const int n0 = blockIdx.x * 64;
    const int tid = threadIdx.x, lane = tid & 31, wid = tid >> 5;
    const int wm = wid >> 2, wn = wid & 3;
    const uint32_t sb = smem_u32(smem);

    int* stok = (int*)smem;
    if (tid < 128) {
        const int m = m0 + tid;
        stok[tid] = g_tok[e * T_DIM + (m < ne ? m : ne - 1)];
    }
    __syncthreads();

    const __half* w1g = g_w1h + ((size_t)e * 2 * I_DIM + n0) * H_DIM;
    const __half* w1l = w1g + (size_t)I_DIM * H_DIM;

    const int c8  = tid & 7;
    const int r32 = tid >> 3;
    const uint32_t swz = (uint32_t)((c8 ^ (r32 & 7)) << 4);
    const __half* asrc[4];
    const __half* bsrc[4];
    uint32_t adst[4], bdst[4];
#pragma unroll
    for (int i = 0; i < 4; i++) {
        const int row = r32 + i * 32;
        asrc[i] = g_normed_h + (size_t)stok[row] * H_DIM + c8 * 8;
        bsrc[i] = ((row < 64) ? (w1g + (size_t)row * H_DIM)
                              : (w1l + (size_t)(row - 64) * H_DIM)) + c8 * 8;
        adst[i] = sb + 1024u + (uint32_t)row * 128u + swz;
        bdst[i] = adst[i] + 16384u;
    }

#define G1_ISSUE(kt, s) do { \
    const uint32_t so = (uint32_t)(s) * STAGE_BYTES; \
    const int ko = (kt) * 64; \
    _Pragma("unroll") \
    for (int i = 0; i < 4; i++) { \
        cp16(adst[i] + so, asrc[i] + ko); \
        cp16(bdst[i] + so, bsrc[i] + ko); \
    } } while (0)

    const int NK = H_DIM / 64;   // 16
    G1_ISSUE(0, 0); CP_COMMIT();
    G1_ISSUE(1, 1); CP_COMMIT();

    float accg[4][2][4] = {}, accl[4][2][4] = {};

    const int lr  = lane & 7;
    const int rA  = ((lane >> 3) & 1) * 8 + lr;
    const int cA  = (lane >> 4);
    const int rB  = ((lane >> 4) & 1) * 8 + lr;
    const int cB  = ((lane >> 3) & 1);

    for (int c = 0; c < NK; c++) {
        CP_WAIT1();
        __syncthreads();
        if (c + 2 < NK) G1_ISSUE(c + 2, (c + 2) % STAGES);
        CP_COMMIT();

        const uint32_t Asm = sb + 1024u + (uint32_t)(c % STAGES) * STAGE_BYTES;
        const uint32_t Bsm = Asm + 16384u;
#pragma unroll
        for (int ks = 0; ks < 4; ks++) {
            uint32_t a[4][4];
            const uint32_t chA = (uint32_t)(((2 * ks + cA) ^ lr) << 4);
#pragma unroll
            for (int mf = 0; mf < 4; mf++) {
                const int row = wm * 64 + mf * 16 + rA;
                ldsm4(a[mf], Asm + (uint32_t)row * 128u + chA);
            }
            uint32_t bg[4], bl[4];
            const uint32_t chB = (uint32_t)(((2 * ks + cB) ^ lr) << 4);
            ldsm4(bg, Bsm + (uint32_t)(wn * 16 + rB) * 128u + chB);
            ldsm4(bl, Bsm + (uint32_t)(64 + wn * 16 + rB) * 128u + chB);
#pragma unroll
            for (int mf = 0; mf < 4; mf++) {
#pragma unroll
                for (int nf = 0; nf < 2; nf++) {
                    mma_f16(accg[mf][nf], a[mf], bg + 2 * nf);
                    mma_f16(accl[mf][nf], a[mf], bl + 2 * nf);
                }
            }
        }
    }

    const float* bgb = b1 + (size_t)e * 2 * I_DIM + n0;
    const float* blb = bgb + I_DIM;
#pragma unroll
    for (int mf = 0; mf < 4; mf++) {
        const int mb = m0 + wm * 64 + mf * 16 + (lane >> 2);
#pragma unroll
        for (int h = 0; h < 2; h++) {
            const int m = mb + h * 8;
            if (m < ne) {
                __half* orow = g_act_h + ((size_t)e * T_DIM + m) * I_DIM + n0;
#pragma unroll
                for (int nf = 0; nf < 2; nf++) {
                    const int nloc = wn * 16 + nf * 8 + 2 * (lane & 3);
                    const float g0 = accg[mf][nf][2 * h + 0] + bgb[nloc];
                    const float g1 = accg[mf][nf][2 * h + 1] + bgb[nloc + 1];
                    const float l0 = accl[mf][nf][2 * h + 0] + blb[nloc];
                    const float l1 = accl[mf][nf][2 * h + 1] + blb[nloc + 1];
                    __half2 o = __floats2half2_rn(swiglu(g0, l0), swiglu(g1, l1));
                    *(__half2*)(orow + nloc) = o;
                }
            }
        }
    }
#undef G1_ISSUE
}

// ---------------- kernel 3: grouped GEMM2 + bias -> g_out2 (fp32) ----------------
__global__ __launch_bounds__(256, 2) void k_gemm2(const float* __restrict__ b2)
{
    extern __shared__ char smem[];
    const int e  = blockIdx.z;
    const int ne = g_cnt[e];
    const int m0 = blockIdx.y * 128;
    if (m0 >= ne) return;
    const int n0 = blockIdx.x * 128;
    const int tid = threadIdx.x, lane = tid & 31, wid = tid >> 5;
    const int wm = wid >> 2, wn = wid & 3;
    const uint32_t sb = smem_u32(smem);

    const __half* a_base = g_act_h + ((size_t)e * T_DIM + m0) * I_DIM;
    const __half* b_base = g_w2h + ((size_t)e * H_DIM + n0) * I_DIM;

    const int c8  = tid & 7;
    const int r32 = tid >> 3;
    const uint32_t swz = (uint32_t)((c8 ^ (r32 & 7)) << 4);
    const __half* asrc[4];
    const __half* bsrc[4];
    uint32_t adst[4], bdst[4];
#pragma unroll
    for (int i = 0; i < 4; i++) {
        const int row = r32 + i * 32;
        asrc[i] = a_base + (size_t)row * I_DIM + c8 * 8;
        bsrc[i] = b_base + (size_t)row * I_DIM + c8 * 8;
        adst[i] = sb + 1024u + (uint32_t)row * 128u + swz;
        bdst[i] = adst[i] + 16384u;
    }

#define G2_ISSUE(kt, s) do { \
    const uint32_t so = (uint32_t)(s) * STAGE_BYTES; \
    const int ko = (kt) * 64; \
    _Pragma("unroll") \
    for (int i = 0; i < 4; i++) { \
        cp16(adst[i] + so, asrc[i] + ko); \
        cp16(bdst[i] + so, bsrc[i] + ko); \
    } } while (0)

    const int NK = I_DIM / 64;   // 32
    G2_ISSUE(0, 0); CP_COMMIT();
    G2_ISSUE(1, 1); CP_COMMIT();

    float acc[4][4][4] = {};

    const int lr  = lane & 7;
    const int rA  = ((lane >> 3) & 1) * 8 + lr;
    const int cA  = (lane >> 4);
    const int rB  = ((lane >> 4) & 1) * 8 + lr;
    const int cB  = ((lane >> 3) & 1);

    for (int c = 0; c < NK; c++) {
        CP_WAIT1();
        __syncthreads();
        if (c + 2 < NK) G2_ISSUE(c + 2, (c + 2) % STAGES);
        CP_COMMIT();

        const uint32_t Asm = sb + 1024u + (uint32_t)(c % STAGES) * STAGE_BYTES;
        const uint32_t Bsm = Asm + 16384u;
#pragma unroll
        for (int ks = 0; ks < 4; ks++) {
            uint32_t a[4][4];
            const uint32_t chA = (uint32_t)(((2 * ks + cA) ^ lr) << 4);
#pragma unroll
            for (int mf = 0; mf < 4; mf++) {
                const int row = wm * 64 + mf * 16 + rA;
                ldsm4(a[mf], Asm + (uint32_t)row * 128u + chA);
            }
            uint32_t b[2][4];
            const uint32_t chB = (uint32_t)(((2 * ks + cB) ^ lr) << 4);
            ldsm4(b[0], Bsm + (uint32_t)(wn * 32 + rB) * 128u + chB);
            ldsm4(b[1], Bsm + (uint32_t)(wn * 32 + 16 + rB) * 128u + chB);
#pragma unroll
            for (int mf = 0; mf < 4; mf++) {
#pragma unroll
                for (int nf = 0; nf < 4; nf++)
                    mma_f16(acc[mf][nf], a[mf], b[nf >> 1] + 2 * (nf & 1));
            }
        }
    }

    const float* bb = b2 + (size_t)e * H_DIM + n0;
#pragma unroll
    for (int mf = 0; mf < 4; mf++) {
        const int mb = m0 + wm * 64 + mf * 16 + (lane >> 2);
#pragma unroll
        for (int h = 0; h < 2; h++) {
            const int m = mb + h * 8;
            if (m < ne) {
                float* orow = g_out2 + ((size_t)e * T_DIM + m) * H_DIM + n0;
#pragma unroll
                for (int nf = 0; nf < 4; nf++) {
                    const int nloc = wn * 32 + nf * 8 + 2 * (lane & 3);
                    float2 o = { acc[mf][nf][2 * h + 0] + bb[nloc],
                                 acc[mf][nf][2 * h + 1] + bb[nloc + 1] };
                    *(float2*)(orow + nloc) = o;
                }
            }
        }
    }
#undef G2_ISSUE
}

// ---------------- kernel 4: gather-combine + residual ----------------
__global__ __launch_bounds__(256) void k_combine(
    const float* __restrict__ x, float* __restrict__ out)
{
    const size_t idx = (size_t)blockIdx.x * blockDim.x + threadIdx.x;
    if (idx >= (size_t)T_DIM * H_DIM / 4) return;
    const int t  = (int)(idx / (H_DIM / 4));
    const int hc = (int)(idx % (H_DIM / 4));

    const int   s0 = g_slot[2 * t + 0], s1 = g_slot[2 * t + 1];
    const float w0 = g_wgt[2 * t + 0],  w1 = g_wgt[2 * t + 1];

    const float4 xv = ((const float4*)x)[idx];
    const float4 o0 = *(const float4*)(g_out2 + (size_t)s0 * H_DIM + hc * 4);
    const float4 o1 = *(const float4*)(g_out2 + (size_t)s1 * H_DIM + hc * 4);
    float4 o;
    o.x = xv.x + w0 * o0.x + w1 * o1.x;
    o.y = xv.y + w0 * o0.y + w1 * o1.y;
    o.z = xv.z + w0 * o0.z + w1 * o1.z;
    o.w = xv.w + w0 * o0.w + w1 * o1.w;
    ((float4*)out)[idx] = o;
}

// ---------------- launch ----------------
extern "C" void kernel_launch(void* const* d_in, const int* in_sizes, int n_in,
                              void* d_out, int out_size)
{
    const float* x     = (const float*)d_in[0];
    const float* scale = (const float*)d_in[1];
    const float* gk    = (const float*)d_in[2];
    const float* gb    = (const float*)d_in[3];
    const float* w1    = (const float*)d_in[4];
    const float* b1    = (const float*)d_in[5];
    const float* w2    = (const float*)d_in[6];
    const float* b2    = (const float*)d_in[7];
    float* out = (float*)d_out;

    cudaFuncSetAttribute(k_gemm1, cudaFuncAttributeMaxDynamicSharedMemorySize, G1_SMEM);
    cudaFuncSetAttribute(k_gemm2, cudaFuncAttributeMaxDynamicSharedMemorySize, G2_SMEM);

    k_zero<<<1, 32>>>();

    {
        __half* w1h_p; cudaGetSymbolAddress((void**)&w1h_p, g_w1h);
        __half* w2h_p; cudaGetSymbolAddress((void**)&w2h_p, g_w2h);
        const int n4_1 = E_DIM * 2 * I_DIM * H_DIM / 4;
        const int n4_2 = E_DIM * H_DIM * I_DIM / 4;
        k_cvt<<<n4_1 / 256, 256>>>((const float4*)w1, (uint2*)w1h_p, n4_1);
        k_cvt<<<n4_2 / 256, 256>>>((const float4*)w2, (uint2*)w2h_p, n4_2);
    }

    k_rms_gate<<<T_DIM / 32, 256>>>(x, scale, gk, gb);

    dim3 g1(I_DIM / 64, T_DIM / 128, E_DIM);    // 32 x 32 x 8
    k_gemm1<<<g1, 256, G1_SMEM>>>(b1);

    dim3 g2(H_DIM / 128, T_DIM / 128, E_DIM);   // 8 x 32 x 8
    k_gemm2<<<g2, 256, G2_SMEM>>>(b2);

    k_combine<<<(T_DIM * H_DIM / 4 + 255) / 256, 256>>>(x, out);
}